// round 6
// baseline (speedup 1.0000x reference)
#include <cuda_runtime.h>
#include <cuda_bf16.h>
#include <mma.h>

using namespace nvcuda;

#define NUM_C 2048
#define LEN_Q 32
#define D 640

// Scratch (no cudaMalloc allowed)
__device__ __nv_bfloat16 g_u_bf[NUM_C * D];   // u = s_b*v_b + k_b  (bf16)
__device__ __nv_bfloat16 g_w_bf[D * D];       // W in bf16
__device__ __nv_bfloat16 g_yg[NUM_C * D];     // yg = (W u + b_fc)*gamma1 (bf16)

#define WCONV_BLOCKS 400   // (640*640/4)/256
#define PREP_BLOCKS  128   // 2048 batches / 16 per block (2 per warp)

// ---------------------------------------------------------------------------
// K1: fused  [blocks 0..399]   W fp32 -> bf16
//            [blocks 400..527] u prep, 2 batches per warp (20 loads in flight)
// ---------------------------------------------------------------------------
__global__ void k_prep(const float* __restrict__ W,
                       const float* __restrict__ v,
                       const float* __restrict__ k) {
    const int t = threadIdx.x;
    if (blockIdx.x < WCONV_BLOCKS) {
        const int i4 = blockIdx.x * 256 + t;
        const float4 w = ((const float4*)W)[i4];
        __nv_bfloat162 p0 = __floats2bfloat162_rn(w.x, w.y);
        __nv_bfloat162 p1 = __floats2bfloat162_rn(w.z, w.w);
        uint2 pk; pk.x = *(unsigned*)&p0; pk.y = *(unsigned*)&p1;
        ((uint2*)g_w_bf)[i4] = pk;
        return;
    }
    const int wid  = (blockIdx.x - WCONV_BLOCKS) * 8 + (t >> 5);
    const int b0   = wid * 2;
    const int b1   = b0 + 1;
    const int lane = t & 31;
    const float4* vp0 = (const float4*)(v + b0 * D);
    const float4* kp0 = (const float4*)(k + b0 * D);
    const float4* vp1 = (const float4*)(v + b1 * D);
    const float4* kp1 = (const float4*)(k + b1 * D);

    float4 va[5], ka[5], vb[5], kb[5];
    #pragma unroll
    for (int j = 0; j < 5; j++) {
        va[j] = vp0[lane + j * 32];
        vb[j] = vp1[lane + j * 32];
        ka[j] = kp0[lane + j * 32];
        kb[j] = kp1[lane + j * 32];
    }
    float s0 = 0.f, s1 = 0.f;
    #pragma unroll
    for (int j = 0; j < 5; j++) {
        s0 += va[j].x + va[j].y + va[j].z + va[j].w;
        s1 += vb[j].x + vb[j].y + vb[j].z + vb[j].w;
    }
    #pragma unroll
    for (int off = 16; off > 0; off >>= 1) {
        s0 += __shfl_xor_sync(~0u, s0, off);
        s1 += __shfl_xor_sync(~0u, s1, off);
    }
    uint2* up0 = (uint2*)(g_u_bf + b0 * D);
    uint2* up1 = (uint2*)(g_u_bf + b1 * D);
    #pragma unroll
    for (int j = 0; j < 5; j++) {
        __nv_bfloat162 a0 = __floats2bfloat162_rn(fmaf(s0, va[j].x, ka[j].x),
                                                  fmaf(s0, va[j].y, ka[j].y));
        __nv_bfloat162 a1 = __floats2bfloat162_rn(fmaf(s0, va[j].z, ka[j].z),
                                                  fmaf(s0, va[j].w, ka[j].w));
        uint2 pa; pa.x = *(unsigned*)&a0; pa.y = *(unsigned*)&a1;
        up0[lane + j * 32] = pa;
        __nv_bfloat162 c0 = __floats2bfloat162_rn(fmaf(s1, vb[j].x, kb[j].x),
                                                  fmaf(s1, vb[j].y, kb[j].y));
        __nv_bfloat162 c1 = __floats2bfloat162_rn(fmaf(s1, vb[j].z, kb[j].z),
                                                  fmaf(s1, vb[j].w, kb[j].w));
        uint2 pc; pc.x = *(unsigned*)&c0; pc.y = *(unsigned*)&c1;
        up1[lane + j * 32] = pc;
    }
}

// ---------------------------------------------------------------------------
// K2: bf16 wmma GEMM, cp.async double-buffered (proven in R4).
// yg[b,j] = (sum_d u[b,d]*W[j,d] + bfc[j])*gam[j], bf16 output.
// Tile 64x64, BK=64, 2 stages, 128 threads (4 warps, each 32x32).
// ---------------------------------------------------------------------------
#define GK_PAD 72   // 64 + 8 bf16 pad

__device__ __forceinline__ void cp_async16(void* smem_dst, const void* gmem_src) {
    unsigned s = (unsigned)__cvta_generic_to_shared(smem_dst);
    asm volatile("cp.async.ca.shared.global [%0], [%1], 16;\n" :: "r"(s), "l"(gmem_src));
}

__global__ __launch_bounds__(128) void k_gemm(const float* __restrict__ bfc,
                                              const float* __restrict__ gam) {
    __shared__ __align__(16) __nv_bfloat16 As[2][64 * GK_PAD];
    __shared__ __align__(16) __nv_bfloat16 Bs[2][64 * GK_PAD];
    __shared__ __align__(16) float Sout[64 * 64];

    const int bm = blockIdx.y * 64;
    const int bn = blockIdx.x * 64;
    const int tid = threadIdx.x;
    const int w  = tid >> 5;
    const int wm_l = (w >> 1) * 32;
    const int wn_l = (w & 1) * 32;

    auto prefetch = [&](int st, int k0) {
        #pragma unroll
        for (int i = 0; i < 4; i++) {
            const int e = tid + i * 128;
            const int r = e >> 3;
            const int c = (e & 7) * 8;
            cp_async16(&As[st][r * GK_PAD + c], &g_u_bf[(bm + r) * D + k0 + c]);
            cp_async16(&Bs[st][r * GK_PAD + c], &g_w_bf[(bn + r) * D + k0 + c]);
        }
        asm volatile("cp.async.commit_group;\n");
    };

    wmma::fragment<wmma::accumulator, 16, 16, 16, float> acc[2][2];
    #pragma unroll
    for (int i = 0; i < 2; i++)
        #pragma unroll
        for (int j = 0; j < 2; j++) wmma::fill_fragment(acc[i][j], 0.0f);

    prefetch(0, 0);

    #pragma unroll 1
    for (int kt = 0; kt < 10; kt++) {
        if (kt + 1 < 10) {
            prefetch((kt + 1) & 1, (kt + 1) * 64);
            asm volatile("cp.async.wait_group 1;\n");
        } else {
            asm volatile("cp.async.wait_group 0;\n");
        }
        __syncthreads();

        const int st = kt & 1;
        #pragma unroll
        for (int kk = 0; kk < 4; kk++) {
            wmma::fragment<wmma::matrix_a, 16, 16, 16, __nv_bfloat16, wmma::row_major> a[2];
            wmma::fragment<wmma::matrix_b, 16, 16, 16, __nv_bfloat16, wmma::col_major> bb[2];
            #pragma unroll
            for (int i = 0; i < 2; i++)
                wmma::load_matrix_sync(a[i], &As[st][(wm_l + i * 16) * GK_PAD + kk * 16], GK_PAD);
            #pragma unroll
            for (int j = 0; j < 2; j++)
                wmma::load_matrix_sync(bb[j], &Bs[st][(wn_l + j * 16) * GK_PAD + kk * 16], GK_PAD);
            #pragma unroll
            for (int i = 0; i < 2; i++)
                #pragma unroll
                for (int j = 0; j < 2; j++)
                    wmma::mma_sync(acc[i][j], a[i], bb[j], acc[i][j]);
        }
        __syncthreads();
    }

    #pragma unroll
    for (int i = 0; i < 2; i++)
        #pragma unroll
        for (int j = 0; j < 2; j++)
            wmma::store_matrix_sync(&Sout[(wm_l + i * 16) * 64 + wn_l + j * 16],
                                    acc[i][j], 64, wmma::mem_row_major);
    __syncthreads();

    #pragma unroll
    for (int i = 0; i < 16; i++) {
        const int e   = tid + i * 128;
        const int r   = e >> 5;
        const int cp  = e & 31;
        const int col = bn + cp * 2;
        const float x0 = (Sout[r * 64 + cp * 2 + 0] + __ldg(&bfc[col + 0])) * __ldg(&gam[col + 0]);
        const float x1 = (Sout[r * 64 + cp * 2 + 1] + __ldg(&bfc[col + 1])) * __ldg(&gam[col + 1]);
        *(__nv_bfloat162*)&g_yg[(bm + r) * D + col] = __floats2bfloat162_rn(x0, x1);
    }
}

// ---------------------------------------------------------------------------
// K3: LayerNorm. Warp-per-row, NO smem staging, NO syncthreads.
// Each thread: 5 float4 q loads (streaming) + 5 uint2 yg loads (L2-resident)
// all independent -> 10 loads in flight. 8192 blocks x 256 threads.
// ---------------------------------------------------------------------------
__global__ void k_ln(const float* __restrict__ q,
                     const float* __restrict__ lnw,
                     const float* __restrict__ lnb,
                     float* __restrict__ out) {
    const int  warp = threadIdx.x >> 5;
    const int  lane = threadIdx.x & 31;
    const long row  = (long)blockIdx.x * 8 + warp;   // 0..65535
    const int  b    = (int)(row >> 5);               // batch = row / 32

    const float4* qrow = (const float4*)(q + row * D);
    const uint2*  ygp  = (const uint2*)(g_yg + b * D);
    float4* orow       = (float4*)(out + row * D);

    // issue all 10 independent loads
    float4 qv[5];
    uint2  yv[5];
    #pragma unroll
    for (int j = 0; j < 5; j++) {
        qv[j] = __ldcs(&qrow[j * 32 + lane]);
        yv[j] = __ldg(&ygp[j * 32 + lane]);
    }

    float z[20];
    float sum = 0.f, sq = 0.f;
    #pragma unroll
    for (int j = 0; j < 5; j++) {
        const float2 y0 = __bfloat1622float2(*(const __nv_bfloat162*)&yv[j].x);
        const float2 y1 = __bfloat1622float2(*(const __nv_bfloat162*)&yv[j].y);
        const float z0 = qv[j].x + y0.x;
        const float z1 = qv[j].y + y0.y;
        const float z2 = qv[j].z + y1.x;
        const float z3 = qv[j].w + y1.y;
        z[j * 4 + 0] = z0; z[j * 4 + 1] = z1; z[j * 4 + 2] = z2; z[j * 4 + 3] = z3;
        sum += z0 + z1 + z2 + z3;
        sq = fmaf(z0, z0, sq); sq = fmaf(z1, z1, sq);
        sq = fmaf(z2, z2, sq); sq = fmaf(z3, z3, sq);
    }
    #pragma unroll
    for (int off = 16; off > 0; off >>= 1) {
        sum += __shfl_xor_sync(~0u, sum, off);
        sq  += __shfl_xor_sync(~0u, sq,  off);
    }
    const float inv_d = 1.0f / (float)D;
    const float mean = sum * inv_d;
    const float var  = sq * inv_d - mean * mean;
    const float rstd = rsqrtf(var + 1e-5f);

    #pragma unroll
    for (int j = 0; j < 5; j++) {
        const int c4 = j * 32 + lane;
        const int c  = c4 * 4;
        float4 o;
        o.x = (z[j * 4 + 0] - mean) * rstd * __ldg(&lnw[c + 0]) + __ldg(&lnb[c + 0]);
        o.y = (z[j * 4 + 1] - mean) * rstd * __ldg(&lnw[c + 1]) + __ldg(&lnb[c + 1]);
        o.z = (z[j * 4 + 2] - mean) * rstd * __ldg(&lnw[c + 2]) + __ldg(&lnb[c + 2]);
        o.w = (z[j * 4 + 3] - mean) * rstd * __ldg(&lnw[c + 3]) + __ldg(&lnb[c + 3]);
        __stcs(&orow[c4], o);
    }
}

// ---------------------------------------------------------------------------
// Inputs: 0=q 1=k 2=v 3=w_fc 4=b_fc 5=gamma1 6=ln_w 7=ln_b
// ---------------------------------------------------------------------------
extern "C" void kernel_launch(void* const* d_in, const int* in_sizes, int n_in,
                              void* d_out, int out_size) {
    const float* q     = (const float*)d_in[0];
    const float* k     = (const float*)d_in[1];
    const float* v     = (const float*)d_in[2];
    const float* w_fc  = (const float*)d_in[3];
    const float* b_fc  = (const float*)d_in[4];
    const float* gam   = (const float*)d_in[5];
    const float* ln_w  = (const float*)d_in[6];
    const float* ln_b  = (const float*)d_in[7];
    float* out = (float*)d_out;

    k_prep<<<WCONV_BLOCKS + PREP_BLOCKS, 256>>>(w_fc, v, k);
    k_gemm<<<dim3(D / 64, NUM_C / 64), 128>>>(b_fc, gam);
    k_ln<<<NUM_C * LEN_Q / 8, 256>>>(q, ln_w, ln_b, out);
}